// round 9
// baseline (speedup 1.0000x reference)
#include <cuda_runtime.h>

#define HH 512
#define WW 512
#define BB 2
#define GRID 512
#define NTHR 512

// Packed row-pass result, one uint16 per pixel:
//   bit15 = mask (1 = fg), bits[0:15) = row distance to nearest OPPOSITE-class
//   pixel (0x7fff sentinel = none in this row). 1 MB, L2-resident.
__device__ unsigned short g_pack16[BB * HH * WW];

// Replay-safe grid barrier: count returns to 0 each pass, gen increases
// monotonically across graph replays (no reset needed).
__device__ unsigned int g_bar_count;
__device__ volatile unsigned int g_bar_gen;

// ---------------------------------------------------------------------------
// Fused SDF kernel. 512 blocks x 512 threads, launch_bounds(512,4):
// 148 SMs x 4 = 592 >= 512 resident blocks -> spin barrier cannot deadlock.
//
// Phase 1 (rows): 2 rows per block via 512-bit bitmask + ffs/clz word scans.
//   Pure ALU/LDS, no latency chain.
// Barrier: 1 atomic/block + generation spin.
// Phase 2 (cols): ONE scan per thread (no serialization). Exact adaptive
//   window (stop when r^2 >= best; any j with (i-j)^2 >= best cannot improve
//   the min), opposite plane only, 2 px/thread per uint32 __ldcg, coalesced.
//   Fused epilogue out = (m ? -1 : +1) * sqrt(best).
// ---------------------------------------------------------------------------
__global__ void __launch_bounds__(NTHR, 4)
sdf_fused(const float* __restrict__ gt, float* __restrict__ out) {
    const int t = threadIdx.x;
    const int bid = blockIdx.x;

    __shared__ unsigned int sw[2][WW / 32];   // two 512-bit row masks

    // ---------------- Phase 1: rows 2*bid, 2*bid+1 ------------------------
    const float v0 = gt[(size_t)(bid * 2 + 0) * WW + t];
    const float v1 = gt[(size_t)(bid * 2 + 1) * WW + t];
    const unsigned int m0 = (v0 == 1.0f) ? 1u : 0u;
    const unsigned int m1 = (v1 == 1.0f) ? 1u : 0u;
    const unsigned int bits0 = __ballot_sync(0xFFFFFFFFu, m0 != 0u);
    const unsigned int bits1 = __ballot_sync(0xFFFFFFFFu, m1 != 0u);
    if ((t & 31) == 0) {
        sw[0][t >> 5] = bits0;
        sw[1][t >> 5] = bits1;
    }
    __syncthreads();

    const int w0 = t >> 5, off = t & 31;
    #pragma unroll
    for (int k = 0; k < 2; ++k) {
        const unsigned int m = k ? m1 : m0;
        const unsigned int xorm = m ? 0xFFFFFFFFu : 0u;
        const unsigned int cur = sw[k][w0] ^ xorm;

        int right = 0x7fff;
        {
            const unsigned int hi = cur & (0xFFFFFFFEu << off);
            if (hi) {
                right = (__ffs(hi) - 1) - off;
            } else {
                #pragma unroll 1
                for (int w = w0 + 1; w < WW / 32; ++w) {
                    const unsigned int q = sw[k][w] ^ xorm;
                    if (q) { right = (w << 5) + (__ffs(q) - 1) - t; break; }
                }
            }
        }
        int left = 0x7fff;
        {
            const unsigned int lo = cur & ((1u << off) - 1u);
            if (lo) {
                left = off - (31 - __clz(lo));
            } else {
                #pragma unroll 1
                for (int w = w0 - 1; w >= 0; --w) {
                    const unsigned int q = sw[k][w] ^ xorm;
                    if (q) { left = t - ((w << 5) + (31 - __clz(q))); break; }
                }
            }
        }

        const unsigned int d = (unsigned int)min(min(left, right), 0x7fff);
        g_pack16[(size_t)(bid * 2 + k) * WW + t] =
            (unsigned short)(d | (m << 15));
    }

    // ---------------- Grid barrier ----------------------------------------
    __syncthreads();
    if (t == 0) {
        __threadfence();                       // publish g_pack16
        const unsigned int old_gen = g_bar_gen;
        if (atomicAdd(&g_bar_count, 1u) == GRID - 1) {
            g_bar_count = 0;
            __threadfence();
            atomicAdd((unsigned int*)&g_bar_gen, 1u);
        } else {
            while (g_bar_gen == old_gen) { }
        }
    }
    __syncthreads();
    __threadfence();                           // acquire: see peers' g_pack16

    // ---------------- Phase 2: ONE column scan per thread -----------------
    const int w = bid * 2 + (t >> 8);          // row-work id: w = b*512 + i
    const int i = w & 511;
    const int pair = t & 255;
    const unsigned int* __restrict__ col =
        reinterpret_cast<const unsigned int*>(g_pack16) +
        (size_t)(w - i) * (WW / 2) + pair;     // (w - i) = b*512

    const unsigned int u = __ldcg(&col[i * (WW / 2)]);
    const unsigned int mA = (u >> 15) & 1u;
    const unsigned int mB = (u >> 31) & 1u;
    const int roA = (int)(u & 0x7fffu);
    const int roB = (int)((u >> 16) & 0x7fffu);
    float bestA = (float)(roA * roA);
    float bestB = (float)(roB * roB);

    #pragma unroll 1
    for (int r = 1; r < HH; ++r) {
        const float rr = (float)(r * r);
        if (rr >= bestA && rr >= bestB) break;
        const int up = i - r, dn = i + r;
        if (up >= 0) {
            const unsigned int q = __ldcg(&col[up * (WW / 2)]);
            const int ra = (int)(q & 0x7fffu), rb = (int)((q >> 16) & 0x7fffu);
            const float fa = (((q >> 15) & 1u) != mA) ? 0.0f : (float)(ra * ra);
            const float fb = (((q >> 31) & 1u) != mB) ? 0.0f : (float)(rb * rb);
            bestA = fminf(bestA, fa + rr);
            bestB = fminf(bestB, fb + rr);
        }
        if (dn < HH) {
            const unsigned int q = __ldcg(&col[dn * (WW / 2)]);
            const int ra = (int)(q & 0x7fffu), rb = (int)((q >> 16) & 0x7fffu);
            const float fa = (((q >> 15) & 1u) != mA) ? 0.0f : (float)(ra * ra);
            const float fb = (((q >> 31) & 1u) != mB) ? 0.0f : (float)(rb * rb);
            bestA = fminf(bestA, fa + rr);
            bestB = fminf(bestB, fb + rr);
        }
    }

    float2 o;
    o.x = (mA ? -1.0f : 1.0f) * sqrtf(bestA);
    o.y = (mB ? -1.0f : 1.0f) * sqrtf(bestB);
    reinterpret_cast<float2*>(out)[(size_t)w * (WW / 2) + pair] = o;
}

extern "C" void kernel_launch(void* const* d_in, const int* in_sizes, int n_in,
                              void* d_out, int out_size) {
    const float* gt = (const float*)d_in[0];
    float* out = (float*)d_out;
    (void)in_sizes; (void)n_in; (void)out_size;

    sdf_fused<<<GRID, NTHR>>>(gt, out);
}